// round 1
// baseline (speedup 1.0000x reference)
#include <cuda_runtime.h>

// Problem dims (fixed per reference)
#define T_DIM 512
#define B_DIM 32
#define I_DIM 512
#define H_DIM 512
#define M_DIM (T_DIM * B_DIM)   // 16384 rows of x
#define N_DIM (3 * H_DIM)       // 1536 gate features
#define K_DIM I_DIM             // 512

// GEMM tiling
#define BM 128
#define BN 128
#define BK 16
#define NKT (K_DIM / BK)        // 32
#define AS_STRIDE 132           // BM + 4 pad
#define BS_STRIDE 132           // BN + 4 pad

// 100 MB scratch for gate pre-activations gx[m, n], m = t*B + b, n = g*H + h
__device__ float g_gx[(size_t)M_DIM * N_DIM];

typedef unsigned long long ull;

__device__ __forceinline__ ull fma2(ull a, ull b, ull c) {
    ull d;
    asm("fma.rn.f32x2 %0, %1, %2, %3;" : "=l"(d) : "l"(a), "l"(b), "l"(c));
    return d;
}
__device__ __forceinline__ ull pack_dup(float x) {
    ull d;
    unsigned int xi = __float_as_uint(x);
    asm("mov.b64 %0, {%1, %2};" : "=l"(d) : "r"(xi), "r"(xi));
    return d;
}
__device__ __forceinline__ void unpack2(ull v, float& x, float& y) {
    unsigned int lo, hi;
    asm("mov.b64 {%0, %1}, %2;" : "=r"(lo), "=r"(hi) : "l"(v));
    x = __uint_as_float(lo);
    y = __uint_as_float(hi);
}

// ---------------------------------------------------------------------------
// GEMM: C[m, n] = sum_k A[m, k] * W[n, k]
// A = x (16384 x 512, row-major, K contiguous)
// W = W_ih (1536 x 512, row-major, K contiguous)
// fp32, packed f32x2 FMA micro-kernel (vectorized pairwise along M).
// ---------------------------------------------------------------------------
__global__ __launch_bounds__(256, 1)
void indgru_gemm(const float* __restrict__ A, const float* __restrict__ W) {
    __shared__ __align__(16) float As[2][BK][AS_STRIDE];
    __shared__ __align__(16) float Bs[2][BK][BS_STRIDE];

    const int tid = threadIdx.x;
    const int bm = blockIdx.x;   // 0..127
    const int bn = blockIdx.y;   // 0..11

    const float* Ab = A + (size_t)bm * BM * K_DIM;
    const float* Bb = W + (size_t)bn * BN * K_DIM;

    // Global-load mapping: 128-row x 16-col tile = 512 float4; 2 per thread per operand
    const int lrow = tid >> 2;   // 0..63
    const int lq   = tid & 3;    // 0..3 (quad of 4 k-values)

    float4 sa0, sa1, sb0, sb1;

    // Compute-thread mapping: 16x16 grid of 8x8 micro-tiles
    const int tx = tid & 15;
    const int ty = tid >> 4;
    const int m0 = ty * 8;
    const int n0 = tx * 8;

    ull acc[4][8];
#pragma unroll
    for (int i = 0; i < 4; ++i)
#pragma unroll
        for (int j = 0; j < 8; ++j) acc[i][j] = 0ull;

    // ---- prologue: load tile 0 ----
    {
        const float* ap = Ab + (size_t)lrow * K_DIM + lq * 4;
        sa0 = *(const float4*)ap;
        sa1 = *(const float4*)(ap + (size_t)64 * K_DIM);
        const float* bp = Bb + (size_t)lrow * K_DIM + lq * 4;
        sb0 = *(const float4*)bp;
        sb1 = *(const float4*)(bp + (size_t)64 * K_DIM);
    }
    {
        As[0][lq * 4 + 0][lrow] = sa0.x; As[0][lq * 4 + 1][lrow] = sa0.y;
        As[0][lq * 4 + 2][lrow] = sa0.z; As[0][lq * 4 + 3][lrow] = sa0.w;
        As[0][lq * 4 + 0][lrow + 64] = sa1.x; As[0][lq * 4 + 1][lrow + 64] = sa1.y;
        As[0][lq * 4 + 2][lrow + 64] = sa1.z; As[0][lq * 4 + 3][lrow + 64] = sa1.w;
        Bs[0][lq * 4 + 0][lrow] = sb0.x; Bs[0][lq * 4 + 1][lrow] = sb0.y;
        Bs[0][lq * 4 + 2][lrow] = sb0.z; Bs[0][lq * 4 + 3][lrow] = sb0.w;
        Bs[0][lq * 4 + 0][lrow + 64] = sb1.x; Bs[0][lq * 4 + 1][lrow + 64] = sb1.y;
        Bs[0][lq * 4 + 2][lrow + 64] = sb1.z; Bs[0][lq * 4 + 3][lrow + 64] = sb1.w;
    }
    __syncthreads();

    int buf = 0;
    for (int kt = 0; kt < NKT; ++kt) {
        // prefetch next tile global -> regs (latency hidden behind compute)
        if (kt + 1 < NKT) {
            const int ko = (kt + 1) * BK;
            const float* ap = Ab + (size_t)lrow * K_DIM + ko + lq * 4;
            sa0 = *(const float4*)ap;
            sa1 = *(const float4*)(ap + (size_t)64 * K_DIM);
            const float* bp = Bb + (size_t)lrow * K_DIM + ko + lq * 4;
            sb0 = *(const float4*)bp;
            sb1 = *(const float4*)(bp + (size_t)64 * K_DIM);
        }

        // compute on current buffer
#pragma unroll
        for (int k = 0; k < BK; ++k) {
            ulonglong2 av0 = *reinterpret_cast<const ulonglong2*>(&As[buf][k][m0]);
            ulonglong2 av1 = *reinterpret_cast<const ulonglong2*>(&As[buf][k][m0 + 4]);
            float4 bv0 = *reinterpret_cast<const float4*>(&Bs[buf][k][n0]);
            float4 bv1 = *reinterpret_cast<const float4*>(&Bs[buf][k][n0 + 4]);
            ull am[4];
            am[0] = av0.x; am[1] = av0.y; am[2] = av1.x; am[3] = av1.y;
            ull bb[8];
            bb[0] = pack_dup(bv0.x); bb[1] = pack_dup(bv0.y);
            bb[2] = pack_dup(bv0.z); bb[3] = pack_dup(bv0.w);
            bb[4] = pack_dup(bv1.x); bb[5] = pack_dup(bv1.y);
            bb[6] = pack_dup(bv1.z); bb[7] = pack_dup(bv1.w);
#pragma unroll
            for (int n = 0; n < 8; ++n)
#pragma unroll
                for (int m2 = 0; m2 < 4; ++m2)
                    acc[m2][n] = fma2(am[m2], bb[n], acc[m2][n]);
        }

        // store prefetched regs into the other buffer (free: last read 1 iter ago)
        if (kt + 1 < NKT) {
            const int nb = buf ^ 1;
            As[nb][lq * 4 + 0][lrow] = sa0.x; As[nb][lq * 4 + 1][lrow] = sa0.y;
            As[nb][lq * 4 + 2][lrow] = sa0.z; As[nb][lq * 4 + 3][lrow] = sa0.w;
            As[nb][lq * 4 + 0][lrow + 64] = sa1.x; As[nb][lq * 4 + 1][lrow + 64] = sa1.y;
            As[nb][lq * 4 + 2][lrow + 64] = sa1.z; As[nb][lq * 4 + 3][lrow + 64] = sa1.w;
            Bs[nb][lq * 4 + 0][lrow] = sb0.x; Bs[nb][lq * 4 + 1][lrow] = sb0.y;
            Bs[nb][lq * 4 + 2][lrow] = sb0.z; Bs[nb][lq * 4 + 3][lrow] = sb0.w;
            Bs[nb][lq * 4 + 0][lrow + 64] = sb1.x; Bs[nb][lq * 4 + 1][lrow + 64] = sb1.y;
            Bs[nb][lq * 4 + 2][lrow + 64] = sb1.z; Bs[nb][lq * 4 + 3][lrow + 64] = sb1.w;
        }
        __syncthreads();
        buf ^= 1;
    }

    // epilogue: acc[m2][n] holds rows (m0+2*m2, m0+2*m2+1) in (lo, hi)
    float* Cb = g_gx + ((size_t)(bm * BM + m0)) * N_DIM + (size_t)bn * BN + n0;
#pragma unroll
    for (int m2 = 0; m2 < 4; ++m2) {
        float lo[8], hi[8];
#pragma unroll
        for (int n = 0; n < 8; ++n) unpack2(acc[m2][n], lo[n], hi[n]);
        float4 v;
        float* r0 = Cb + (size_t)(2 * m2) * N_DIM;
        float* r1 = r0 + N_DIM;
        v.x = lo[0]; v.y = lo[1]; v.z = lo[2]; v.w = lo[3]; *(float4*)r0 = v;
        v.x = lo[4]; v.y = lo[5]; v.z = lo[6]; v.w = lo[7]; *(float4*)(r0 + 4) = v;
        v.x = hi[0]; v.y = hi[1]; v.z = hi[2]; v.w = hi[3]; *(float4*)r1 = v;
        v.x = hi[4]; v.y = hi[5]; v.z = hi[6]; v.w = hi[7]; *(float4*)(r1 + 4) = v;
    }
}

// ---------------------------------------------------------------------------
// Scan: one thread per (b, h). Diagonal recurrence, T=512 sequential steps.
// Depth-4 register prefetch ring hides gx load latency behind compute chains.
// ---------------------------------------------------------------------------
__global__ __launch_bounds__(128)
void indgru_scan(const float* __restrict__ h0, const float* __restrict__ w_hh,
                 float* __restrict__ out) {
    const int idx = blockIdx.x * 128 + threadIdx.x;   // 0..16383
    const int b = idx >> 9;                            // / H_DIM
    const int h = idx & (H_DIM - 1);

    const float wr = w_hh[h];
    const float wz = w_hh[H_DIM + h];
    const float wn = w_hh[2 * H_DIM + h];

    float hv = h0[idx];

    const float* gbase = g_gx + (size_t)b * N_DIM + h;  // stride per t: B*3H
    const int TSTRIDE = B_DIM * N_DIM;                  // 49152

    const int PF = 4;
    float bgr[PF], bgz[PF], bgn[PF];
#pragma unroll
    for (int i = 0; i < PF; ++i) {
        const float* gp = gbase + (size_t)i * TSTRIDE;
        bgr[i] = gp[0];
        bgz[i] = gp[H_DIM];
        bgn[i] = gp[2 * H_DIM];
    }

    float* op = out + idx;

#pragma unroll 4
    for (int t = 0; t < T_DIM; ++t) {
        const int s = t & 3;
        float gr = bgr[s], gz = bgz[s], gn = bgn[s];

        const int tp = t + PF;
        if (tp < T_DIM) {
            const float* gp = gbase + (size_t)tp * TSTRIDE;
            bgr[s] = gp[0];
            bgz[s] = gp[H_DIM];
            bgn[s] = gp[2 * H_DIM];
        }

        float ar = fminf(fmaxf(gr + wr * hv, -30.f), 30.f);
        float az = fminf(fmaxf(gz + wz * hv, -30.f), 30.f);
        float r = __fdividef(1.f, 1.f + __expf(-ar));
        float z = __fdividef(1.f, 1.f + __expf(-az));
        float an = fminf(fmaxf(gn + r * (wn * hv), -15.f), 15.f);
        float e2 = __expf(2.f * an);
        float n = 1.f - __fdividef(2.f, e2 + 1.f);
        hv = z * (hv - n) + n;

        op[(size_t)t * (B_DIM * H_DIM)] = hv;
    }
    // trailing h_last block (B, H) after the (T, B, H) outputs
    op[(size_t)T_DIM * (B_DIM * H_DIM)] = hv;
}

// ---------------------------------------------------------------------------
extern "C" void kernel_launch(void* const* d_in, const int* in_sizes, int n_in,
                              void* d_out, int out_size) {
    const float* x    = (const float*)d_in[0];   // (T, B, I)
    const float* h0   = (const float*)d_in[1];   // (B, H)
    const float* W_ih = (const float*)d_in[2];   // (3H, I)
    const float* w_hh = (const float*)d_in[3];   // (3, H)
    float* out = (float*)d_out;                  // (T, B, H) then (1, B, H)

    dim3 grid(M_DIM / BM, N_DIM / BN);           // 128 x 12
    indgru_gemm<<<grid, 256>>>(x, W_ih);
    indgru_scan<<<(B_DIM * H_DIM) / 128, 128>>>(h0, w_hh, out);
}

// round 3
// speedup vs baseline: 1.8932x; 1.8932x over previous
#include <cuda_runtime.h>
#include <cuda_bf16.h>
#include <cstdint>

// Problem dims (fixed per reference)
#define T_DIM 512
#define B_DIM 32
#define I_DIM 512
#define H_DIM 512
#define M_DIM (T_DIM * B_DIM)   // 16384
#define N_DIM (3 * H_DIM)       // 1536
#define K_DIM I_DIM             // 512

// ---------------------------------------------------------------------------
// Device scratch (no allocs allowed)
// ---------------------------------------------------------------------------
__device__ float         g_gx[(size_t)M_DIM * N_DIM];          // 100 MB
__device__ __nv_bfloat16 g_Ahi[(size_t)M_DIM * K_DIM];         // 16 MB
__device__ __nv_bfloat16 g_Alo[(size_t)M_DIM * K_DIM];         // 16 MB
__device__ __nv_bfloat16 g_Bhi[(size_t)N_DIM * K_DIM];         // 1.5 MB
__device__ __nv_bfloat16 g_Blo[(size_t)N_DIM * K_DIM];         // 1.5 MB

// ---------------------------------------------------------------------------
// PTX helpers (baseline-PTX features only: cp.async, ldmatrix, mma.sync)
// ---------------------------------------------------------------------------
__device__ __forceinline__ uint32_t smem_u32(const void* p) {
    uint32_t a;
    asm("{ .reg .u64 t; cvta.to.shared.u64 t, %1; cvt.u32.u64 %0, t; }"
        : "=r"(a) : "l"(p));
    return a;
}
__device__ __forceinline__ void cpa16(uint32_t dst, const void* src) {
    asm volatile("cp.async.cg.shared.global [%0], [%1], 16;"
                 :: "r"(dst), "l"(src));
}
__device__ __forceinline__ void cpa_commit() {
    asm volatile("cp.async.commit_group;" ::: "memory");
}
template <int N>
__device__ __forceinline__ void cpa_wait() {
    asm volatile("cp.async.wait_group %0;" :: "n"(N) : "memory");
}
__device__ __forceinline__ void ldm4(uint32_t* r, uint32_t addr) {
    asm volatile("ldmatrix.sync.aligned.m8n8.x4.shared.b16 {%0,%1,%2,%3}, [%4];"
                 : "=r"(r[0]), "=r"(r[1]), "=r"(r[2]), "=r"(r[3]) : "r"(addr));
}
__device__ __forceinline__ void mma_bf16(float* c, const uint32_t* a,
                                         const uint32_t* b) {
    asm volatile(
        "mma.sync.aligned.m16n8k16.row.col.f32.bf16.bf16.f32 "
        "{%0,%1,%2,%3}, {%4,%5,%6,%7}, {%8,%9}, {%0,%1,%2,%3};"
        : "+f"(c[0]), "+f"(c[1]), "+f"(c[2]), "+f"(c[3])
        : "r"(a[0]), "r"(a[1]), "r"(a[2]), "r"(a[3]), "r"(b[0]), "r"(b[1]));
}

// ---------------------------------------------------------------------------
// Split conversion: v -> bf16 hi + bf16 lo (residual)
// ---------------------------------------------------------------------------
__device__ __forceinline__ unsigned short f2b_split(float v, unsigned short& lo_out) {
    __nv_bfloat16 h = __float2bfloat16(v);
    float r = v - __bfloat162float(h);
    __nv_bfloat16 l = __float2bfloat16(r);
    lo_out = *reinterpret_cast<unsigned short*>(&l);
    return *reinterpret_cast<unsigned short*>(&h);
}

__global__ void convert_split_A(const float4* __restrict__ src) {
    ushort4* hi = reinterpret_cast<ushort4*>(g_Ahi);
    ushort4* lo = reinterpret_cast<ushort4*>(g_Alo);
    const int n4 = (M_DIM * K_DIM) / 4;
    const int stride = gridDim.x * blockDim.x;
    for (int i = blockIdx.x * blockDim.x + threadIdx.x; i < n4; i += stride) {
        float4 v = src[i];
        ushort4 h, l;
        h.x = f2b_split(v.x, l.x);
        h.y = f2b_split(v.y, l.y);
        h.z = f2b_split(v.z, l.z);
        h.w = f2b_split(v.w, l.w);
        hi[i] = h; lo[i] = l;
    }
}
__global__ void convert_split_B(const float4* __restrict__ src) {
    ushort4* hi = reinterpret_cast<ushort4*>(g_Bhi);
    ushort4* lo = reinterpret_cast<ushort4*>(g_Blo);
    const int n4 = (N_DIM * K_DIM) / 4;
    const int stride = gridDim.x * blockDim.x;
    for (int i = blockIdx.x * blockDim.x + threadIdx.x; i < n4; i += stride) {
        float4 v = src[i];
        ushort4 h, l;
        h.x = f2b_split(v.x, l.x);
        h.y = f2b_split(v.y, l.y);
        h.z = f2b_split(v.z, l.z);
        h.w = f2b_split(v.w, l.w);
        hi[i] = h; lo[i] = l;
    }
}

// ---------------------------------------------------------------------------
// HMMA GEMM: gx[m, n] = x[m, :] . W[n, :] via 3-pass bf16 split (mma.sync)
// CTA 128x128, 8 warps (2x4, warp tile 64x32), BK=32, double-buffered cp.async.
// Smem rows padded to 80 B -> conflict-free ldmatrix.
// ---------------------------------------------------------------------------
#define GBM 128
#define GBN 128
#define GBK 32
#define NSTAGE (K_DIM / GBK)       // 16
#define ROWB 80                    // smem row stride in bytes (32 bf16 + pad)
#define ARR_BYTES (128 * ROWB)     // 10240
#define STAGE_BYTES (4 * ARR_BYTES)// 40960: [Ahi][Alo][Bhi][Blo]
#define GEMM_SMEM (2 * STAGE_BYTES)// 81920

__device__ __forceinline__ void load_stage(uint32_t sb, int buf, int kt,
                                           int mbase, int nbase, int tid) {
    const int k0 = kt * GBK;
    const uint32_t dst0 = sb + buf * STAGE_BYTES;
    const __nv_bfloat16* srcs[4] = {
        g_Ahi + (size_t)mbase * K_DIM + k0,
        g_Alo + (size_t)mbase * K_DIM + k0,
        g_Bhi + (size_t)nbase * K_DIM + k0,
        g_Blo + (size_t)nbase * K_DIM + k0,
    };
#pragma unroll
    for (int arr = 0; arr < 4; ++arr) {
#pragma unroll
        for (int j = 0; j < 2; ++j) {
            int unit = tid + j * 256;        // 0..511
            int row = unit >> 2, u = unit & 3;
            cpa16(dst0 + arr * ARR_BYTES + row * ROWB + u * 16,
                  srcs[arr] + (size_t)row * K_DIM + u * 8);
        }
    }
    cpa_commit();
}

__global__ __launch_bounds__(256) void indgru_gemm_mma() {
    extern __shared__ __align__(128) char smem[];
    const uint32_t sb = smem_u32(smem);
    const int tid = threadIdx.x;
    const int wid = tid >> 5;
    const int lid = tid & 31;
    const int mbase = blockIdx.x * GBM;
    const int nbase = blockIdx.y * GBN;

    const int m_warp = (wid >> 2) * 64;    // 0 or 64
    const int n_warp = (wid & 3) * 32;     // 0..96

    // ldmatrix per-lane address components
    const int rowA = m_warp + (lid & 7) + ((lid >> 3) & 1) * 8;
    const int koffA = ((lid >> 4) & 1) * 8;
    const uint32_t aBase = rowA * ROWB + koffA * 2;        // + mf*16*ROWB + ks*32
    const int rowBm = n_warp + (lid & 7) + ((lid >> 4) & 1) * 8;
    const int koffB = ((lid >> 3) & 1) * 8;
    const uint32_t bBase = rowBm * ROWB + koffB * 2;       // + nfp*16*ROWB + ks*32

    float c[4][4][4];
#pragma unroll
    for (int i = 0; i < 4; ++i)
#pragma unroll
        for (int j = 0; j < 4; ++j)
#pragma unroll
            for (int q = 0; q < 4; ++q) c[i][j][q] = 0.f;

    load_stage(sb, 0, 0, mbase, nbase, tid);

    for (int kt = 0; kt < NSTAGE; ++kt) {
        const int buf = kt & 1;
        if (kt + 1 < NSTAGE) {
            load_stage(sb, buf ^ 1, kt + 1, mbase, nbase, tid);
            cpa_wait<1>();
        } else {
            cpa_wait<0>();
        }
        __syncthreads();

        const uint32_t st = sb + buf * STAGE_BYTES;
#pragma unroll
        for (int ks = 0; ks < 2; ++ks) {
            uint32_t Ah[4][4], Al[4][4], Bh[2][4], Bl[2][4];
#pragma unroll
            for (int mf = 0; mf < 4; ++mf) {
                uint32_t ao = aBase + mf * (16 * ROWB) + ks * 32;
                ldm4(Ah[mf], st + 0 * ARR_BYTES + ao);
                ldm4(Al[mf], st + 1 * ARR_BYTES + ao);
            }
#pragma unroll
            for (int nfp = 0; nfp < 2; ++nfp) {
                uint32_t bo = bBase + nfp * (16 * ROWB) + ks * 32;
                ldm4(Bh[nfp], st + 2 * ARR_BYTES + bo);
                ldm4(Bl[nfp], st + 3 * ARR_BYTES + bo);
            }
#pragma unroll
            for (int mf = 0; mf < 4; ++mf) {
#pragma unroll
                for (int nfp = 0; nfp < 2; ++nfp) {
#pragma unroll
                    for (int hf = 0; hf < 2; ++hf) {
                        const int nf = nfp * 2 + hf;
                        mma_bf16(c[mf][nf], Ah[mf], &Bh[nfp][hf * 2]);
                        mma_bf16(c[mf][nf], Ah[mf], &Bl[nfp][hf * 2]);
                        mma_bf16(c[mf][nf], Al[mf], &Bh[nfp][hf * 2]);
                    }
                }
            }
        }
        __syncthreads();
    }

    // epilogue: c[mf][nf] -> g_gx
    const int g = lid >> 2, t = lid & 3;
#pragma unroll
    for (int mf = 0; mf < 4; ++mf) {
        const int m0 = mbase + m_warp + mf * 16 + g;
        float* r0 = g_gx + (size_t)m0 * N_DIM + nbase + n_warp;
        float* r1 = r0 + (size_t)8 * N_DIM;
#pragma unroll
        for (int nf = 0; nf < 4; ++nf) {
            const int nc = nf * 8 + 2 * t;
            *reinterpret_cast<float2*>(r0 + nc) =
                make_float2(c[mf][nf][0], c[mf][nf][1]);
            *reinterpret_cast<float2*>(r1 + nc) =
                make_float2(c[mf][nf][2], c[mf][nf][3]);
        }
    }
}

// ---------------------------------------------------------------------------
// Scan: one thread per (b, h); diagonal recurrence over T=512 steps.
// Depth-8 register prefetch ring, streaming load/store hints.
// ---------------------------------------------------------------------------
__global__ __launch_bounds__(128)
void indgru_scan(const float* __restrict__ h0, const float* __restrict__ w_hh,
                 float* __restrict__ out) {
    const int idx = blockIdx.x * 128 + threadIdx.x;   // 0..16383
    const int b = idx >> 9;
    const int h = idx & (H_DIM - 1);

    const float wr = w_hh[h];
    const float wz = w_hh[H_DIM + h];
    const float wn = w_hh[2 * H_DIM + h];

    float hv = h0[idx];

    const float* gbase = g_gx + (size_t)b * N_DIM + h;
    const int TSTRIDE = B_DIM * N_DIM;                 // 49152

    const int PF = 8;
    float bgr[PF], bgz[PF], bgn[PF];
#pragma unroll
    for (int i = 0; i < PF; ++i) {
        const float* gp = gbase + (size_t)i * TSTRIDE;
        bgr[i] = __ldcs(gp);
        bgz[i] = __ldcs(gp + H_DIM);
        bgn[i] = __ldcs(gp + 2 * H_DIM);
    }

    float* op = out + idx;

#pragma unroll 8
    for (int t = 0; t < T_DIM; ++t) {
        const int s = t & 7;
        float gr = bgr[s], gz = bgz[s], gn = bgn[s];

        const int tp = t + PF;
        if (tp < T_DIM) {
            const float* gp = gbase + (size_t)tp * TSTRIDE;
            bgr[s] = __ldcs(gp);
            bgz[s] = __ldcs(gp + H_DIM);
            bgn[s] = __ldcs(gp + 2 * H_DIM);
        }

        float ar = fminf(fmaxf(gr + wr * hv, -30.f), 30.f);
        float az = fminf(fmaxf(gz + wz * hv, -30.f), 30.f);
        float r = __fdividef(1.f, 1.f + __expf(-ar));
        float z = __fdividef(1.f, 1.f + __expf(-az));
        float an = fminf(fmaxf(gn + r * (wn * hv), -15.f), 15.f);
        float e2 = __expf(2.f * an);
        float n = 1.f - __fdividef(2.f, e2 + 1.f);
        hv = z * (hv - n) + n;

        __stcs(op + (size_t)t * (B_DIM * H_DIM), hv);
    }
    __stcs(op + (size_t)T_DIM * (B_DIM * H_DIM), hv);
}

// ---------------------------------------------------------------------------
extern "C" void kernel_launch(void* const* d_in, const int* in_sizes, int n_in,
                              void* d_out, int out_size) {
    const float* x    = (const float*)d_in[0];   // (T, B, I)
    const float* h0   = (const float*)d_in[1];   // (B, H)
    const float* W_ih = (const float*)d_in[2];   // (3H, I)
    const float* w_hh = (const float*)d_in[3];   // (3, H)
    float* out = (float*)d_out;

    convert_split_A<<<2048, 256>>>((const float4*)x);
    convert_split_B<<<768, 256>>>((const float4*)W_ih);

    cudaFuncSetAttribute(indgru_gemm_mma,
                         cudaFuncAttributeMaxDynamicSharedMemorySize, GEMM_SMEM);
    dim3 grid(M_DIM / GBM, N_DIM / GBN);   // 128 x 12
    indgru_gemm_mma<<<grid, 256, GEMM_SMEM>>>();

    indgru_scan<<<(B_DIM * H_DIM) / 128, 128>>>(h0, w_hh, out);
}